// round 8
// baseline (speedup 1.0000x reference)
#include <cuda_runtime.h>
#include <cuda_fp16.h>
#include <cstdint>

// ---------------------------------------------------------------------------
// Problem constants
// ---------------------------------------------------------------------------
#define BATCH 2
#define SEQ   4096
#define DIM   256
#define NROWS (BATCH * SEQ)        // 8192 rows per view
#define NVIEW 3
#define NVB   (NVIEW * BATCH)      // 6 attention slices
#define IN3   (NVIEW * DIM)        // 768
#define NB    8
#define KCOMB (IN3 + IN3 * NB)     // 6912
#define QKVN  (3 * DIM)            // 768 packed q|k|v columns
#define ROWS3 (NVIEW * NROWS)      // 24576

// ---------------------------------------------------------------------------
// Device scratch (static only -- no cudaMalloc allowed)
// ---------------------------------------------------------------------------
__device__ __half g_tok [(size_t)ROWS3 * DIM];        // fp16 tokens (concat views)
__device__ __half g_wqkv[(size_t)QKVN * DIM];         // packed [wq;wk;wv] fp16
__device__ float  g_bqkv[QKVN];
__device__ __half g_qkv [(size_t)ROWS3 * QKVN];       // 37.7 MB [row][q|k|v]
__device__ __half g_vt  [(size_t)NVB * DIM * SEQ];    // 12.5 MB V^T per slice
__device__ float  g_x   [(size_t)NROWS * IN3];        // LN outputs (concat)
__device__ __half g_a   [(size_t)NROWS * KCOMB];      // 113 MB
__device__ __half g_w   [(size_t)DIM * KCOMB];

// ---------------------------------------------------------------------------
// Async / mma helpers
// ---------------------------------------------------------------------------
__device__ __forceinline__ void cp16(void* smem_dst, const void* gsrc) {
    uint32_t d = (uint32_t)__cvta_generic_to_shared(smem_dst);
    asm volatile("cp.async.cg.shared.global [%0], [%1], 16;" :: "r"(d), "l"(gsrc));
}
__device__ __forceinline__ void cp_commit() { asm volatile("cp.async.commit_group;"); }
template <int N>
__device__ __forceinline__ void cp_wait() { asm volatile("cp.async.wait_group %0;" :: "n"(N)); }

__device__ __forceinline__ void mma_f16(float c[4],
                                        uint32_t a0, uint32_t a1, uint32_t a2, uint32_t a3,
                                        uint32_t b0, uint32_t b1) {
    asm("mma.sync.aligned.m16n8k16.row.col.f32.f16.f16.f32 "
        "{%0,%1,%2,%3}, {%4,%5,%6,%7}, {%8,%9}, {%0,%1,%2,%3};"
        : "+f"(c[0]), "+f"(c[1]), "+f"(c[2]), "+f"(c[3])
        : "r"(a0), "r"(a1), "r"(a2), "r"(a3), "r"(b0), "r"(b1));
}

// ---------------------------------------------------------------------------
// FP16 tensor-core GEMM (NT): C = A @ B^T (+bias), fp32 accumulate.
// Unchanged from R7 (proven): 128x128x32 tiles, 3-stage cp.async, pad-40 rows.
// ---------------------------------------------------------------------------
#define STAGES 3
#define AROW   40
#define STG_H  (128 * AROW)

template <bool OUTH>
__global__ __launch_bounds__(256, 2)
void hgemm(const __half* __restrict__ A, int lda,
           const __half* __restrict__ B, int ldb,
           void* __restrict__ Cv, int ldc, int K,
           long sA, long sB, long sC,
           const float* __restrict__ bias)
{
    A += (long)blockIdx.z * sA;
    B += (long)blockIdx.z * sB;

    extern __shared__ __half sm[];
    __half* Asm = sm;
    __half* Bsm = sm + STAGES * STG_H;

    const int bm = blockIdx.y * 128;
    const int bn = blockIdx.x * 128;

    const int tid  = threadIdx.x;
    const int warp = tid >> 5, lane = tid & 31;
    const int wm = warp & 3;
    const int wn = warp >> 2;
    const int g = lane >> 2, t = lane & 3;

    const int r0 = tid >> 2;
    const int q8 = (tid & 3) * 8;

    float acc[2][8][4] = {};
    const int niter = K >> 5;

    auto fetch = [&](int stage, int k0) {
        __half* as = Asm + stage * STG_H;
        __half* bs = Bsm + stage * STG_H;
        #pragma unroll
        for (int j = 0; j < 2; ++j) {
            const int r = r0 + 64 * j;
            cp16(&as[r * AROW + q8], A + (long)(bm + r) * lda + k0 + q8);
            cp16(&bs[r * AROW + q8], B + (long)(bn + r) * ldb + k0 + q8);
        }
    };

    #pragma unroll
    for (int s = 0; s < STAGES - 1; ++s) {
        if (s < niter) fetch(s, s * 32);
        cp_commit();
    }

    for (int i = 0; i < niter; ++i) {
        cp_wait<STAGES - 2>();
        __syncthreads();

        const int pf = i + STAGES - 1;
        if (pf < niter) fetch(pf % STAGES, pf * 32);
        cp_commit();

        const __half* as = Asm + (i % STAGES) * STG_H;
        const __half* bs = Bsm + (i % STAGES) * STG_H;

        #pragma unroll
        for (int ks = 0; ks < 2; ++ks) {
            const int kk = ks * 16 + 2 * t;
            uint32_t a[2][4];
            #pragma unroll
            for (int mt = 0; mt < 2; ++mt) {
                const int m = wm * 32 + mt * 16 + g;
                const uint32_t* p0 = (const uint32_t*)&as[m * AROW + kk];
                const uint32_t* p1 = (const uint32_t*)&as[(m + 8) * AROW + kk];
                a[mt][0] = p0[0];
                a[mt][1] = p1[0];
                a[mt][2] = p0[4];
                a[mt][3] = p1[4];
            }
            uint32_t b[8][2];
            #pragma unroll
            for (int nt = 0; nt < 8; ++nt) {
                const int n = wn * 64 + nt * 8 + g;
                const uint32_t* pb = (const uint32_t*)&bs[n * AROW + kk];
                b[nt][0] = pb[0];
                b[nt][1] = pb[4];
            }
            #pragma unroll
            for (int mt = 0; mt < 2; ++mt)
                #pragma unroll
                for (int nt = 0; nt < 8; ++nt)
                    mma_f16(acc[mt][nt], a[mt][0], a[mt][1], a[mt][2], a[mt][3],
                            b[nt][0], b[nt][1]);
        }
        __syncthreads();
    }

    #pragma unroll
    for (int mt = 0; mt < 2; ++mt) {
        const int m = bm + wm * 32 + mt * 16 + g;
        #pragma unroll
        for (int nt = 0; nt < 8; ++nt) {
            const int n = bn + wn * 64 + nt * 8 + 2 * t;
            float bx = 0.f, by = 0.f;
            if (bias) { bx = bias[n]; by = bias[n + 1]; }
            const float v0 = acc[mt][nt][0] + bx, v1 = acc[mt][nt][1] + by;
            const float v2 = acc[mt][nt][2] + bx, v3 = acc[mt][nt][3] + by;
            if (OUTH) {
                __half* C = (__half*)Cv + blockIdx.z * sC;
                *(__half2*)(C + (long)m * ldc + n)       = __floats2half2_rn(v0, v1);
                *(__half2*)(C + (long)(m + 8) * ldc + n) = __floats2half2_rn(v2, v3);
            } else {
                float* C = (float*)Cv + blockIdx.z * sC;
                *(float2*)(C + (long)m * ldc + n)       = make_float2(v0, v1);
                *(float2*)(C + (long)(m + 8) * ldc + n) = make_float2(v2, v3);
            }
        }
    }
}

// ---------------------------------------------------------------------------
// Flash attention + fused residual LayerNorm.
// Grid: (SEQ/BR, NVB). 256 threads = 8 warps. 1 CTA/SM (186 KB smem).
// Per CTA: BR=64 queries, loop over SEQ in BC=64 key tiles.
//   S-phase: warp (wm=warp&3, wn=warp>>2) computes S[16 rows][32 cols].
//   Online softmax: row stats (m, l, rescale f) in smem; P staged fp16 in smem.
//   PV-phase: each warp owns a 32-wide d-slice of O[64][256] in registers.
//   Epilogue: O/l staged to smem; LN(O + tokens) written to concat x buffer.
// ---------------------------------------------------------------------------
#define BR    64
#define BC    64
#define QLD   264                 // halfs: 256 + 8 pad (Q/K rows)
#define VLD   72                  // halfs: 64 + 8 pad  (V^T rows: d-major)
#define PLD   72
#define NITER (SEQ / BC)          // 64
#define FLASH_SMEM ((BR*QLD + 2*BC*QLD + 2*DIM*VLD + BR*PLD) * 2 + 7 * BR * 4)

struct FlashParams {
    const __half* qkv;
    const __half* vt;
    float* x;
    const float* tok[NVIEW];
    const float* lng[NVIEW];
    const float* lnb[NVIEW];
};

__global__ __launch_bounds__(256, 1)
void flash_kernel(FlashParams P)
{
    const int slice = blockIdx.y;              // vi*2 + b
    const int q0 = blockIdx.x * BR;
    const size_t base = (size_t)slice * SEQ * QKVN;
    const __half* Qg = P.qkv + base + (size_t)q0 * QKVN;   // [q][d], q offset cols 0..255
    const __half* Kg = P.qkv + base + DIM;                 // [key][d]
    const __half* Vg = P.vt + (size_t)slice * DIM * SEQ;   // [d][key]

    extern __shared__ __half sm[];
    __half* Qs = sm;                              // BR * QLD
    __half* Ks = Qs + BR * QLD;                   // 2 * BC * QLD
    __half* Vs = Ks + 2 * BC * QLD;               // 2 * DIM * VLD
    __half* Ps = Vs + 2 * DIM * VLD;              // BR * PLD
    float* sm_m = (float*)(Ps + BR * PLD);        // BR
    float* sm_l = sm_m + BR;                      // BR
    float* sm_f = sm_l + BR;                      // BR
    float* pmax = sm_f + BR;                      // 2*BR
    float* psum = pmax + 2 * BR;                  // 2*BR

    const int tid  = threadIdx.x;
    const int warp = tid >> 5, lane = tid & 31;
    const int wm = warp & 3, wn = warp >> 2;
    const int g = lane >> 2, t = lane & 3;
    const int lr = tid >> 2, lc = tid & 3;

    auto loadQ = [&] {
        #pragma unroll
        for (int j = 0; j < 8; ++j) {
            const int ch = lc + 4 * j;
            cp16(&Qs[lr * QLD + ch * 8], Qg + (size_t)lr * QKVN + ch * 8);
        }
    };
    auto loadK = [&](int it, int buf) {
        __half* ks = Ks + buf * BC * QLD;
        const __half* src = Kg + (size_t)(it * BC) * QKVN;
        #pragma unroll
        for (int j = 0; j < 8; ++j) {
            const int ch = lc + 4 * j;
            cp16(&ks[lr * QLD + ch * 8], src + (size_t)lr * QKVN + ch * 8);
        }
    };
    auto loadV = [&](int it, int buf) {
        __half* vs = Vs + buf * DIM * VLD;
        const __half* src = Vg + it * BC;
        #pragma unroll
        for (int j = 0; j < 8; ++j)
            cp16(&vs[tid * VLD + j * 8], src + (size_t)tid * SEQ + j * 8);
    };

    // prologue: group0 = Q + K0 + V0, group1 = K1 + V1
    loadQ(); loadK(0, 0); loadV(0, 0); cp_commit();
    loadK(1, 1); loadV(1, 1); cp_commit();
    if (tid < BR) { sm_m[tid] = -1e30f; sm_l[tid] = 0.f; }

    float o[4][4][4] = {};     // warp's O slice: rows mt*16+{g,g+8}, d = warp*32+nt*8+2t

    for (int it = 0; it < NITER; ++it) {
        cp_wait<1>();
        __syncthreads();
        const __half* ks = Ks + (it & 1) * BC * QLD;
        const __half* vs = Vs + (it & 1) * DIM * VLD;

        // ---- S = (Q @ K^T) * 1/16 : warp tile 16x32 ----
        float s_acc[4][4] = {};
        #pragma unroll
        for (int ksn = 0; ksn < 16; ++ksn) {
            const int kk = ksn * 16 + 2 * t;
            const __half* qa = &Qs[(wm * 16 + g) * QLD + kk];
            const uint32_t a0 = *(const uint32_t*)qa;
            const uint32_t a1 = *(const uint32_t*)(qa + 8 * QLD);
            const uint32_t a2 = *(const uint32_t*)(qa + 8);
            const uint32_t a3 = *(const uint32_t*)(qa + 8 * QLD + 8);
            #pragma unroll
            for (int nt = 0; nt < 4; ++nt) {
                const __half* kb = &ks[(wn * 32 + nt * 8 + g) * QLD + kk];
                mma_f16(s_acc[nt], a0, a1, a2, a3,
                        *(const uint32_t*)kb, *(const uint32_t*)(kb + 8));
            }
        }
        #pragma unroll
        for (int nt = 0; nt < 4; ++nt)
            #pragma unroll
            for (int c = 0; c < 4; ++c) s_acc[nt][c] *= 0.0625f;

        // ---- row max (warp partial over 32 cols, combine across wn pair) ----
        float mx0 = -1e30f, mx1 = -1e30f;
        #pragma unroll
        for (int nt = 0; nt < 4; ++nt) {
            mx0 = fmaxf(mx0, fmaxf(s_acc[nt][0], s_acc[nt][1]));
            mx1 = fmaxf(mx1, fmaxf(s_acc[nt][2], s_acc[nt][3]));
        }
        mx0 = fmaxf(mx0, __shfl_xor_sync(~0u, mx0, 1));
        mx0 = fmaxf(mx0, __shfl_xor_sync(~0u, mx0, 2));
        mx1 = fmaxf(mx1, __shfl_xor_sync(~0u, mx1, 1));
        mx1 = fmaxf(mx1, __shfl_xor_sync(~0u, mx1, 2));
        if (t == 0) {
            pmax[wn * BR + wm * 16 + g]     = mx0;
            pmax[wn * BR + wm * 16 + g + 8] = mx1;
        }
        __syncthreads();
        if (tid < BR) {
            const float mt_ = fmaxf(pmax[tid], pmax[BR + tid]);
            const float mo = sm_m[tid];
            const float mn = fmaxf(mo, mt_);
            sm_m[tid] = mn;
            sm_f[tid] = __expf(mo - mn);
        }
        __syncthreads();

        // ---- P = exp(S - m), stage to smem, partial row sums ----
        const float m0 = sm_m[wm * 16 + g], m1 = sm_m[wm * 16 + g + 8];
        float sum0 = 0.f, sum1 = 0.f;
        #pragma unroll
        for (int nt = 0; nt < 4; ++nt) {
            const float p00 = __expf(s_acc[nt][0] - m0);
            const float p01 = __expf(s_acc[nt][1] - m0);
            const float p10 = __expf(s_acc[nt][2] - m1);
            const float p11 = __expf(s_acc[nt][3] - m1);
            sum0 += p00 + p01; sum1 += p10 + p11;
            const int c = wn * 32 + nt * 8 + 2 * t;
            *(__half2*)&Ps[(wm * 16 + g) * PLD + c]     = __floats2half2_rn(p00, p01);
            *(__half2*)&Ps[(wm * 16 + g + 8) * PLD + c] = __floats2half2_rn(p10, p11);
        }
        sum0 += __shfl_xor_sync(~0u, sum0, 1);
        sum0 += __shfl_xor_sync(~0u, sum0, 2);
        sum1 += __shfl_xor_sync(~0u, sum1, 1);
        sum1 += __shfl_xor_sync(~0u, sum1, 2);
        if (t == 0) {
            psum[wn * BR + wm * 16 + g]     = sum0;
            psum[wn * BR + wm * 16 + g + 8] = sum1;
        }
        __syncthreads();
        if (tid < BR)
            sm_l[tid] = sm_l[tid] * sm_f[tid] + psum[tid] + psum[BR + tid];

        // ---- rescale O, accumulate P @ V (warp d-slice = warp*32) ----
        float f[8];
        #pragma unroll
        for (int mt = 0; mt < 4; ++mt) {
            f[2 * mt]     = sm_f[mt * 16 + g];
            f[2 * mt + 1] = sm_f[mt * 16 + g + 8];
        }
        #pragma unroll
        for (int mt = 0; mt < 4; ++mt)
            #pragma unroll
            for (int nt = 0; nt < 4; ++nt) {
                o[mt][nt][0] *= f[2 * mt];
                o[mt][nt][1] *= f[2 * mt];
                o[mt][nt][2] *= f[2 * mt + 1];
                o[mt][nt][3] *= f[2 * mt + 1];
            }
        #pragma unroll
        for (int ksn = 0; ksn < 4; ++ksn) {
            const int kk = ksn * 16 + 2 * t;
            uint32_t b0[4], b1[4];
            #pragma unroll
            for (int nt = 0; nt < 4; ++nt) {
                const __half* vb = &vs[(warp * 32 + nt * 8 + g) * VLD + kk];
                b0[nt] = *(const uint32_t*)vb;
                b1[nt] = *(const uint32_t*)(vb + 8);
            }
            #pragma unroll
            for (int mt = 0; mt < 4; ++mt) {
                const __half* pa = &Ps[(mt * 16 + g) * PLD + kk];
                const uint32_t a0 = *(const uint32_t*)pa;
                const uint32_t a1 = *(const uint32_t*)(pa + 8 * PLD);
                const uint32_t a2 = *(const uint32_t*)(pa + 8);
                const uint32_t a3 = *(const uint32_t*)(pa + 8 * PLD + 8);
                #pragma unroll
                for (int nt = 0; nt < 4; ++nt)
                    mma_f16(o[mt][nt], a0, a1, a2, a3, b0[nt], b1[nt]);
            }
        }
        __syncthreads();     // all reads of this K/V buffer done before refill
        if (it + 2 < NITER) { loadK(it + 2, it & 1); loadV(it + 2, it & 1); }
        cp_commit();
    }

    // ---- epilogue: O/l -> smem, then fused residual + LayerNorm -> x ----
    float* Os = (float*)sm;                       // [BR][264] floats (over Qs/Ks)
    {
        float linv[8];
        #pragma unroll
        for (int mt = 0; mt < 4; ++mt) {
            linv[2 * mt]     = 1.f / sm_l[mt * 16 + g];
            linv[2 * mt + 1] = 1.f / sm_l[mt * 16 + g + 8];
        }
        #pragma unroll
        for (int mt = 0; mt < 4; ++mt)
            #pragma unroll
            for (int nt = 0; nt < 4; ++nt) {
                const int r = mt * 16 + g, c = warp * 32 + nt * 8 + 2 * t;
                Os[r * 264 + c]           = o[mt][nt][0] * linv[2 * mt];
                Os[r * 264 + c + 1]       = o[mt][nt][1] * linv[2 * mt];
                Os[(r + 8) * 264 + c]     = o[mt][nt][2] * linv[2 * mt + 1];
                Os[(r + 8) * 264 + c + 1] = o[mt][nt][3] * linv[2 * mt + 1];
            }
    }
    __syncthreads();

    const int view = slice >> 1, bat = slice & 1;
    const float* tokp = P.tok[view] + ((size_t)bat * SEQ + q0) * DIM;
    const float* lg = P.lng[view];
    const float* lb = P.lnb[view];

    const int row = tid >> 2, sub = tid & 3;
    float* orow = Os + row * 264;
    const float* trow = tokp + (size_t)row * DIM;

    float s1 = 0.f;
    #pragma unroll
    for (int i = 0; i < 64; ++i) {
        const int c = sub + 4 * i;
        const float v = orow[c] + trow[c];
        orow[c] = v;
        s1 += v;
    }
    s1 += __shfl_xor_sync(~0u, s1, 1);
    s1 += __shfl_xor_sync(~0u, s1, 2);
    const float mean = s1 * (1.f / DIM);

    float s2 = 0.f;
    #pragma unroll
    for (int i = 0; i < 64; ++i) {
        const float d = orow[sub + 4 * i] - mean;
        s2 += d * d;
    }
    s2 += __shfl_xor_sync(~0u, s2, 1);
    s2 += __shfl_xor_sync(~0u, s2, 2);
    const float rstd = rsqrtf(s2 * (1.f / DIM) + 1e-5f);

    float* xrow = P.x + ((size_t)bat * SEQ + q0 + row) * IN3 + (size_t)view * DIM;
    #pragma unroll
    for (int i = 0; i < 64; ++i) {
        const int c = sub + 4 * i;
        xrow[c] = (orow[c] - mean) * rstd * lg[c] + lb[c];
    }
}

// ---------------------------------------------------------------------------
// Transpose V slices: qkv[slice][key][512+d] -> vt[slice][d][key]  (fp16)
// ---------------------------------------------------------------------------
__global__ __launch_bounds__(256)
void transpose_v(const __half* __restrict__ qkv, __half* __restrict__ vt)
{
    __shared__ __half tile[32][40];
    const int s  = blockIdx.z;
    const __half* src = qkv + (size_t)s * SEQ * QKVN + 2 * DIM;
    __half* dst = vt + (size_t)s * DIM * SEQ;
    const int k0 = blockIdx.x * 32, d0 = blockIdx.y * 32;
    const int tx = threadIdx.x & 31, ty = threadIdx.x >> 5;
    #pragma unroll
    for (int j = 0; j < 4; ++j)
        tile[ty + 8 * j][tx] = src[(size_t)(k0 + ty + 8 * j) * QKVN + d0 + tx];
    __syncthreads();
    #pragma unroll
    for (int j = 0; j < 4; ++j)
        dst[(size_t)(d0 + ty + 8 * j) * SEQ + k0 + tx] = tile[tx][ty + 8 * j];
}

// ---------------------------------------------------------------------------
// Round-copy fp32 tokens -> fp16 scratch
// ---------------------------------------------------------------------------
__global__ __launch_bounds__(256)
void round_copy_h(const float* __restrict__ src, __half* __restrict__ dst, int n)
{
    const int i = blockIdx.x * 1024 + threadIdx.x * 4;
    if (i >= n) return;
    float4 v = *(const float4*)(src + i);
    *(__half2*)(dst + i)     = __floats2half2_rn(v.x, v.y);
    *(__half2*)(dst + i + 2) = __floats2half2_rn(v.z, v.w);
}

// ---------------------------------------------------------------------------
// Pack [wq;wk;wv] -> g_wqkv (fp16) and biases -> g_bqkv (fp32)
// ---------------------------------------------------------------------------
__global__ __launch_bounds__(256)
void build_wqkv(const float* __restrict__ wq, const float* __restrict__ wk,
                const float* __restrict__ wv, const float* __restrict__ bq,
                const float* __restrict__ bk, const float* __restrict__ bv,
                __half* __restrict__ W, float* __restrict__ Bb)
{
    const int idx = blockIdx.x * 256 + threadIdx.x;
    if (idx >= QKVN * DIM) return;
    const int r = idx / DIM, c = idx % DIM;
    const float* w = (r < DIM) ? wq : (r < 2 * DIM) ? wk : wv;
    W[idx] = __float2half_rn(w[(r & (DIM - 1)) * DIM + c]);
    if (idx < QKVN) {
        const float* b = (idx < DIM) ? bq : (idx < 2 * DIM) ? bk : bv;
        Bb[idx] = b[idx & (DIM - 1)];
    }
}

// ---------------------------------------------------------------------------
// Combined weight: [base_w | spline_w * scaler] -> fp16
// ---------------------------------------------------------------------------
__global__ __launch_bounds__(256)
void build_w_kernel(const float* __restrict__ bw, const float* __restrict__ sw,
                    const float* __restrict__ sc, __half* __restrict__ W)
{
    const long idx = (long)blockIdx.x * blockDim.x + threadIdx.x;
    if (idx >= (long)DIM * IN3) return;
    const int o = (int)(idx / IN3);
    const int i = (int)(idx % IN3);
    W[(long)o * KCOMB + i] = __float2half_rn(bw[(long)o * IN3 + i]);
    const float s = sc[(long)o * IN3 + i];
    const float* swp = sw + ((long)o * IN3 + i) * NB;
    __half* wp = W + (long)o * KCOMB + IN3 + (long)i * NB;
    #pragma unroll
    for (int f = 0; f < NB; ++f) wp[f] = __float2half_rn(swp[f] * s);
}

// ---------------------------------------------------------------------------
// Combined A: [silu(x) | cubic b-spline bases] -> fp16
// ---------------------------------------------------------------------------
__global__ __launch_bounds__(256)
void build_a_kernel(const float* __restrict__ x, __half* __restrict__ A)
{
    const long idx = (long)blockIdx.x * blockDim.x + threadIdx.x;
    if (idx >= (long)NROWS * IN3) return;
    const long n = idx / IN3;
    const int i = (int)(idx % IN3);
    const float v = x[idx];

    const float sig = 1.f / (1.f + __expf(-v));
    A[n * KCOMB + i] = __float2half_rn(v * sig);

    const float h = 0.4f;
    float b[11];
    #pragma unroll
    for (int j = 0; j < 11; ++j) {
        const float gj  = -1.f + (j - 3) * h;
        const float gj1 = -1.f + (j - 2) * h;
        b[j] = (v >= gj && v < gj1) ? 1.f : 0.f;
    }
    #pragma unroll
    for (int k = 1; k <= 3; ++k) {
        #pragma unroll
        for (int j = 0; j <= 10 - k; ++j) {
            const float gj   = -1.f + (j - 3) * h;
            const float gjk  = -1.f + (j - 3 + k) * h;
            const float gj1  = -1.f + (j - 2) * h;
            const float gjk1 = -1.f + (j - 2 + k) * h;
            b[j] = (v - gj) / (gjk - gj) * b[j] + (gjk1 - v) / (gjk1 - gj1) * b[j + 1];
        }
    }
    __half* ap = A + n * KCOMB + IN3 + (long)i * NB;
    #pragma unroll
    for (int f = 0; f < NB; ++f) ap[f] = __float2half_rn(b[f]);
}

// ---------------------------------------------------------------------------
// Host launcher
// ---------------------------------------------------------------------------
extern "C" void kernel_launch(void* const* d_in, const int* in_sizes, int n_in,
                              void* d_out, int out_size)
{
    (void)in_sizes; (void)n_in; (void)out_size;

    const float* tok[NVIEW] = {(const float*)d_in[0], (const float*)d_in[1], (const float*)d_in[2]};
    const float* wq = (const float*)d_in[3];
    const float* bq = (const float*)d_in[4];
    const float* wk = (const float*)d_in[5];
    const float* bk = (const float*)d_in[6];
    const float* wv = (const float*)d_in[7];
    const float* bv = (const float*)d_in[8];
    // d_in[9] = view_emb: per-query constant bias -> softmax-invariant -> unused
    const float* lng[NVIEW] = {(const float*)d_in[10], (const float*)d_in[12], (const float*)d_in[14]};
    const float* lnb[NVIEW] = {(const float*)d_in[11], (const float*)d_in[13], (const float*)d_in[15]};
    const float* bw = (const float*)d_in[16];
    const float* sw = (const float*)d_in[17];
    const float* sc = (const float*)d_in[18];

    __half *ptok, *pwqkv, *pqkv, *pvt, *pa, *pw;
    float *pbqkv, *x;
    cudaGetSymbolAddress((void**)&ptok,  g_tok);
    cudaGetSymbolAddress((void**)&pwqkv, g_wqkv);
    cudaGetSymbolAddress((void**)&pbqkv, g_bqkv);
    cudaGetSymbolAddress((void**)&pqkv,  g_qkv);
    cudaGetSymbolAddress((void**)&pvt,   g_vt);
    cudaGetSymbolAddress((void**)&x,     g_x);
    cudaGetSymbolAddress((void**)&pa,    g_a);
    cudaGetSymbolAddress((void**)&pw,    g_w);

    const int SMEM = STAGES * STG_H * 2 * (int)sizeof(__half);   // 61440 B
    cudaFuncSetAttribute(hgemm<true>,  cudaFuncAttributeMaxDynamicSharedMemorySize, SMEM);
    cudaFuncSetAttribute(hgemm<false>, cudaFuncAttributeMaxDynamicSharedMemorySize, SMEM);
    cudaFuncSetAttribute(flash_kernel, cudaFuncAttributeMaxDynamicSharedMemorySize, FLASH_SMEM);

    // 0) pack tokens (fp16) and qkv weights
    const int ntok = NROWS * DIM;
    for (int vi = 0; vi < NVIEW; ++vi)
        round_copy_h<<<(ntok + 1023) / 1024, 256>>>(tok[vi], ptok + (long)vi * ntok, ntok);
    build_wqkv<<<(QKVN * DIM + 255) / 256, 256>>>(wq, wk, wv, bq, bk, bv, pwqkv, pbqkv);

    // 1) fused QKV: [24576,768] = tok @ Wqkv^T + bqkv -> fp16
    {
        dim3 grid(QKVN / 128, ROWS3 / 128, 1);
        hgemm<true><<<grid, 256, SMEM>>>(ptok, DIM, pwqkv, DIM, pqkv, QKVN,
                                         DIM, 0, 0, 0, pbqkv);
    }

    // 1b) transpose V slices -> g_vt
    {
        dim3 grid(SEQ / 32, DIM / 32, NVB);
        transpose_v<<<grid, 256>>>(pqkv, pvt);
    }

    // 2) flash attention + residual LN -> concat x (replaces QK/softmax/PV/LN)
    {
        FlashParams fp;
        fp.qkv = pqkv; fp.vt = pvt; fp.x = x;
        for (int vi = 0; vi < NVIEW; ++vi) {
            fp.tok[vi] = tok[vi];
            fp.lng[vi] = lng[vi];
            fp.lnb[vi] = lnb[vi];
        }
        dim3 grid(SEQ / BR, NVB, 1);
        flash_kernel<<<grid, 256, FLASH_SMEM>>>(fp);
    }

    // 3) combined weight / combined A (fp16)
    build_w_kernel<<<(DIM * IN3 + 255) / 256, 256>>>(bw, sw, sc, pw);
    build_a_kernel<<<(int)(((long)NROWS * IN3 + 255) / 256), 256>>>(x, pa);

    // 4) out = A @ W^T (base + spline fused, K = 6912, fp32 out)
    {
        dim3 grid(DIM / 128, NROWS / 128, 1);
        hgemm<false><<<grid, 256, SMEM>>>(pa, KCOMB, pw, KCOMB, (float*)d_out, DIM,
                                          KCOMB, 0, 0, 0, nullptr);
    }
}

// round 9
// speedup vs baseline: 1.9194x; 1.9194x over previous
#include <cuda_runtime.h>
#include <cuda_fp16.h>
#include <cstdint>

// ---------------------------------------------------------------------------
// Problem constants
// ---------------------------------------------------------------------------
#define BATCH 2
#define SEQ   4096
#define DIM   256
#define NROWS (BATCH * SEQ)        // 8192 rows per view
#define NVIEW 3
#define NVB   (NVIEW * BATCH)      // 6 attention slices
#define IN3   (NVIEW * DIM)        // 768
#define NB    8
#define KCOMB (IN3 + IN3 * NB)     // 6912
#define QKVN  (3 * DIM)            // 768 packed q|k|v columns
#define ROWS3 (NVIEW * NROWS)      // 24576

// ---------------------------------------------------------------------------
// Device scratch (static only -- no cudaMalloc allowed)
// ---------------------------------------------------------------------------
__device__ __half g_tok [(size_t)ROWS3 * DIM];        // fp16 tokens (concat views)
__device__ __half g_wqkv[(size_t)QKVN * DIM];         // packed [wq;wk;wv] fp16
__device__ float  g_bqkv[QKVN];
__device__ __half g_qkv [(size_t)ROWS3 * QKVN];       // 37.7 MB [row][q|k|v]
__device__ __half g_vt  [(size_t)NVB * DIM * SEQ];    // 12.5 MB V^T per slice
__device__ __half g_s   [(size_t)NVB * SEQ * SEQ];    // 202 MB fp16 scores->probs
__device__ float  g_att [(size_t)ROWS3 * DIM];
__device__ float  g_x   [(size_t)NROWS * IN3];
__device__ __half g_a   [(size_t)NROWS * KCOMB];      // 113 MB
__device__ __half g_w   [(size_t)DIM * KCOMB];
__device__ float  g_part[2][(size_t)NROWS * DIM];     // split-K partials (50 MB)

// ---------------------------------------------------------------------------
// Async / mma helpers
// ---------------------------------------------------------------------------
__device__ __forceinline__ void cp16(void* smem_dst, const void* gsrc) {
    uint32_t d = (uint32_t)__cvta_generic_to_shared(smem_dst);
    asm volatile("cp.async.cg.shared.global [%0], [%1], 16;" :: "r"(d), "l"(gsrc));
}
__device__ __forceinline__ void cp_commit() { asm volatile("cp.async.commit_group;"); }
template <int N>
__device__ __forceinline__ void cp_wait() { asm volatile("cp.async.wait_group %0;" :: "n"(N)); }

__device__ __forceinline__ void mma_f16(float c[4],
                                        uint32_t a0, uint32_t a1, uint32_t a2, uint32_t a3,
                                        uint32_t b0, uint32_t b1) {
    asm("mma.sync.aligned.m16n8k16.row.col.f32.f16.f16.f32 "
        "{%0,%1,%2,%3}, {%4,%5,%6,%7}, {%8,%9}, {%0,%1,%2,%3};"
        : "+f"(c[0]), "+f"(c[1]), "+f"(c[2]), "+f"(c[3])
        : "r"(a0), "r"(a1), "r"(a2), "r"(a3), "r"(b0), "r"(b1));
}

// ---------------------------------------------------------------------------
// FP16 tensor-core GEMM (NT): C = A @ B^T (+bias), fp32 accumulate.
// 128x128x32 tiles, 4-stage cp.async pipeline, pad-40 rows, 2 CTAs/SM.
// ---------------------------------------------------------------------------
#define STAGES 4
#define AROW   40
#define STG_H  (128 * AROW)

template <bool OUTH>
__global__ __launch_bounds__(256, 2)
void hgemm(const __half* __restrict__ A, int lda,
           const __half* __restrict__ B, int ldb,
           void* __restrict__ Cv, int ldc, int K,
           long sA, long sB, long sC,
           const float* __restrict__ bias)
{
    A += (long)blockIdx.z * sA;
    B += (long)blockIdx.z * sB;

    extern __shared__ __half sm[];
    __half* Asm = sm;
    __half* Bsm = sm + STAGES * STG_H;

    const int bm = blockIdx.y * 128;
    const int bn = blockIdx.x * 128;

    const int tid  = threadIdx.x;
    const int warp = tid >> 5, lane = tid & 31;
    const int wm = warp & 3;
    const int wn = warp >> 2;
    const int g = lane >> 2, t = lane & 3;

    const int r0 = tid >> 2;
    const int q8 = (tid & 3) * 8;

    float acc[2][8][4] = {};
    const int niter = K >> 5;

    auto fetch = [&](int stage, int k0) {
        __half* as = Asm + stage * STG_H;
        __half* bs = Bsm + stage * STG_H;
        #pragma unroll
        for (int j = 0; j < 2; ++j) {
            const int r = r0 + 64 * j;
            cp16(&as[r * AROW + q8], A + (long)(bm + r) * lda + k0 + q8);
            cp16(&bs[r * AROW + q8], B + (long)(bn + r) * ldb + k0 + q8);
        }
    };

    #pragma unroll
    for (int s = 0; s < STAGES - 1; ++s) {
        if (s < niter) fetch(s, s * 32);
        cp_commit();
    }

    for (int i = 0; i < niter; ++i) {
        cp_wait<STAGES - 2>();
        __syncthreads();

        const int pf = i + STAGES - 1;
        if (pf < niter) fetch(pf % STAGES, pf * 32);
        cp_commit();

        const __half* as = Asm + (i % STAGES) * STG_H;
        const __half* bs = Bsm + (i % STAGES) * STG_H;

        #pragma unroll
        for (int ks = 0; ks < 2; ++ks) {
            const int kk = ks * 16 + 2 * t;
            uint32_t a[2][4];
            #pragma unroll
            for (int mt = 0; mt < 2; ++mt) {
                const int m = wm * 32 + mt * 16 + g;
                const uint32_t* p0 = (const uint32_t*)&as[m * AROW + kk];
                const uint32_t* p1 = (const uint32_t*)&as[(m + 8) * AROW + kk];
                a[mt][0] = p0[0];
                a[mt][1] = p1[0];
                a[mt][2] = p0[4];
                a[mt][3] = p1[4];
            }
            uint32_t b[8][2];
            #pragma unroll
            for (int nt = 0; nt < 8; ++nt) {
                const int n = wn * 64 + nt * 8 + g;
                const uint32_t* pb = (const uint32_t*)&bs[n * AROW + kk];
                b[nt][0] = pb[0];
                b[nt][1] = pb[4];
            }
            #pragma unroll
            for (int mt = 0; mt < 2; ++mt)
                #pragma unroll
                for (int nt = 0; nt < 8; ++nt)
                    mma_f16(acc[mt][nt], a[mt][0], a[mt][1], a[mt][2], a[mt][3],
                            b[nt][0], b[nt][1]);
        }
        __syncthreads();
    }

    #pragma unroll
    for (int mt = 0; mt < 2; ++mt) {
        const int m = bm + wm * 32 + mt * 16 + g;
        #pragma unroll
        for (int nt = 0; nt < 8; ++nt) {
            const int n = bn + wn * 64 + nt * 8 + 2 * t;
            float bx = 0.f, by = 0.f;
            if (bias) { bx = bias[n]; by = bias[n + 1]; }
            const float v0 = acc[mt][nt][0] + bx, v1 = acc[mt][nt][1] + by;
            const float v2 = acc[mt][nt][2] + bx, v3 = acc[mt][nt][3] + by;
            if (OUTH) {
                __half* C = (__half*)Cv + blockIdx.z * sC;
                *(__half2*)(C + (long)m * ldc + n)       = __floats2half2_rn(v0, v1);
                *(__half2*)(C + (long)(m + 8) * ldc + n) = __floats2half2_rn(v2, v3);
            } else {
                float* C = (float*)Cv + blockIdx.z * sC;
                *(float2*)(C + (long)m * ldc + n)       = make_float2(v0, v1);
                *(float2*)(C + (long)(m + 8) * ldc + n) = make_float2(v2, v3);
            }
        }
    }
}

// ---------------------------------------------------------------------------
// Transpose V slices: qkv[slice][key][512+d] -> vt[slice][d][key]  (fp16)
// ---------------------------------------------------------------------------
__global__ __launch_bounds__(256)
void transpose_v(const __half* __restrict__ qkv, __half* __restrict__ vt)
{
    __shared__ __half tile[32][40];
    const int s  = blockIdx.z;
    const __half* src = qkv + (size_t)s * SEQ * QKVN + 2 * DIM;
    __half* dst = vt + (size_t)s * DIM * SEQ;
    const int k0 = blockIdx.x * 32, d0 = blockIdx.y * 32;
    const int tx = threadIdx.x & 31, ty = threadIdx.x >> 5;
    #pragma unroll
    for (int j = 0; j < 4; ++j)
        tile[ty + 8 * j][tx] = src[(size_t)(k0 + ty + 8 * j) * QKVN + d0 + tx];
    __syncthreads();
    #pragma unroll
    for (int j = 0; j < 4; ++j)
        dst[(size_t)(d0 + ty + 8 * j) * SEQ + k0 + tx] = tile[tx][ty + 8 * j];
}

// ---------------------------------------------------------------------------
// Row softmax over fp16 scores, in place: p = softmax(s / 16).
// Row = 4096 halfs, 256 threads -> 16 halfs (2x uint4) per thread.
// ---------------------------------------------------------------------------
__global__ __launch_bounds__(256)
void softmax_h(__half* __restrict__ S, float scale)
{
    __half* row = S + (size_t)blockIdx.x * SEQ;
    const int tid = threadIdx.x;
    __shared__ float red[8];

    float v[16];
    #pragma unroll
    for (int j = 0; j < 2; ++j) {
        const __half2* p = (const __half2*)(row + (j * 256 + tid) * 8);
        #pragma unroll
        for (int q = 0; q < 4; ++q) {
            const float2 f = __half22float2(p[q]);
            v[j * 8 + 2 * q]     = f.x;
            v[j * 8 + 2 * q + 1] = f.y;
        }
    }

    float m = -1e30f;
    #pragma unroll
    for (int i = 0; i < 16; ++i) m = fmaxf(m, v[i]);
    #pragma unroll
    for (int o = 16; o; o >>= 1) m = fmaxf(m, __shfl_xor_sync(0xffffffffu, m, o));
    if ((tid & 31) == 0) red[tid >> 5] = m;
    __syncthreads();
    m = red[0];
    #pragma unroll
    for (int i = 1; i < 8; ++i) m = fmaxf(m, red[i]);
    __syncthreads();

    float sum = 0.f;
    #pragma unroll
    for (int i = 0; i < 16; ++i) {
        v[i] = __expf(scale * (v[i] - m));
        sum += v[i];
    }
    #pragma unroll
    for (int o = 16; o; o >>= 1) sum += __shfl_xor_sync(0xffffffffu, sum, o);
    if ((tid & 31) == 0) red[tid >> 5] = sum;
    __syncthreads();
    sum = 0.f;
    #pragma unroll
    for (int i = 0; i < 8; ++i) sum += red[i];
    const float inv = 1.f / sum;

    #pragma unroll
    for (int j = 0; j < 2; ++j) {
        __half2* p = (__half2*)(row + (j * 256 + tid) * 8);
        #pragma unroll
        for (int q = 0; q < 4; ++q)
            p[q] = __floats2half2_rn(v[j * 8 + 2 * q] * inv, v[j * 8 + 2 * q + 1] * inv);
    }
}

// ---------------------------------------------------------------------------
// Round-copy fp32 tokens -> fp16 scratch
// ---------------------------------------------------------------------------
__global__ __launch_bounds__(256)
void round_copy_h(const float* __restrict__ src, __half* __restrict__ dst, int n)
{
    const int i = blockIdx.x * 1024 + threadIdx.x * 4;
    if (i >= n) return;
    float4 v = *(const float4*)(src + i);
    *(__half2*)(dst + i)     = __floats2half2_rn(v.x, v.y);
    *(__half2*)(dst + i + 2) = __floats2half2_rn(v.z, v.w);
}

// ---------------------------------------------------------------------------
// Pack [wq;wk;wv] -> g_wqkv (fp16) and biases -> g_bqkv (fp32)
// ---------------------------------------------------------------------------
__global__ __launch_bounds__(256)
void build_wqkv(const float* __restrict__ wq, const float* __restrict__ wk,
                const float* __restrict__ wv, const float* __restrict__ bq,
                const float* __restrict__ bk, const float* __restrict__ bv,
                __half* __restrict__ W, float* __restrict__ Bb)
{
    const int idx = blockIdx.x * 256 + threadIdx.x;
    if (idx >= QKVN * DIM) return;
    const int r = idx / DIM, c = idx % DIM;
    const float* w = (r < DIM) ? wq : (r < 2 * DIM) ? wk : wv;
    W[idx] = __float2half_rn(w[(r & (DIM - 1)) * DIM + c]);
    if (idx < QKVN) {
        const float* b = (idx < DIM) ? bq : (idx < 2 * DIM) ? bk : bv;
        Bb[idx] = b[idx & (DIM - 1)];
    }
}

// ---------------------------------------------------------------------------
// y = LayerNorm(att + tokens) * g + b -> concatenated x buffer (fp32)
// ---------------------------------------------------------------------------
__global__ __launch_bounds__(256)
void resid_ln_kernel(const float* __restrict__ att, const float* __restrict__ tok,
                     const float* __restrict__ g, const float* __restrict__ b,
                     float* __restrict__ xout, int view)
{
    const long row = blockIdx.x;
    const int d = threadIdx.x;
    __shared__ float red[8];

    const float v = att[row * DIM + d] + tok[row * DIM + d];

    float s = v;
    #pragma unroll
    for (int o = 16; o; o >>= 1) s += __shfl_xor_sync(0xffffffffu, s, o);
    if ((d & 31) == 0) red[d >> 5] = s;
    __syncthreads();
    float mean = 0.f;
    #pragma unroll
    for (int i = 0; i < 8; ++i) mean += red[i];
    mean *= (1.f / DIM);
    __syncthreads();

    const float c = v - mean;
    float s2 = c * c;
    #pragma unroll
    for (int o = 16; o; o >>= 1) s2 += __shfl_xor_sync(0xffffffffu, s2, o);
    if ((d & 31) == 0) red[d >> 5] = s2;
    __syncthreads();
    float var = 0.f;
    #pragma unroll
    for (int i = 0; i < 8; ++i) var += red[i];
    var *= (1.f / DIM);

    const float y = c * rsqrtf(var + 1e-5f) * g[d] + b[d];
    xout[row * IN3 + (long)view * DIM + d] = y;
}

// ---------------------------------------------------------------------------
// Combined weight: [base_w | spline_w * scaler] -> fp16
// ---------------------------------------------------------------------------
__global__ __launch_bounds__(256)
void build_w_kernel(const float* __restrict__ bw, const float* __restrict__ sw,
                    const float* __restrict__ sc, __half* __restrict__ W)
{
    const long idx = (long)blockIdx.x * blockDim.x + threadIdx.x;
    if (idx >= (long)DIM * IN3) return;
    const int o = (int)(idx / IN3);
    const int i = (int)(idx % IN3);
    W[(long)o * KCOMB + i] = __float2half_rn(bw[(long)o * IN3 + i]);
    const float s = sc[(long)o * IN3 + i];
    const float* swp = sw + ((long)o * IN3 + i) * NB;
    __half* wp = W + (long)o * KCOMB + IN3 + (long)i * NB;
    #pragma unroll
    for (int f = 0; f < NB; ++f) wp[f] = __float2half_rn(swp[f] * s);
}

// ---------------------------------------------------------------------------
// Combined A: [silu(x) | cubic b-spline bases] -> fp16
// ---------------------------------------------------------------------------
__global__ __launch_bounds__(256)
void build_a_kernel(const float* __restrict__ x, __half* __restrict__ A)
{
    const long idx = (long)blockIdx.x * blockDim.x + threadIdx.x;
    if (idx >= (long)NROWS * IN3) return;
    const long n = idx / IN3;
    const int i = (int)(idx % IN3);
    const float v = x[idx];

    const float sig = 1.f / (1.f + __expf(-v));
    A[n * KCOMB + i] = __float2half_rn(v * sig);

    const float h = 0.4f;
    float b[11];
    #pragma unroll
    for (int j = 0; j < 11; ++j) {
        const float gj  = -1.f + (j - 3) * h;
        const float gj1 = -1.f + (j - 2) * h;
        b[j] = (v >= gj && v < gj1) ? 1.f : 0.f;
    }
    #pragma unroll
    for (int k = 1; k <= 3; ++k) {
        #pragma unroll
        for (int j = 0; j <= 10 - k; ++j) {
            const float gj   = -1.f + (j - 3) * h;
            const float gjk  = -1.f + (j - 3 + k) * h;
            const float gj1  = -1.f + (j - 2) * h;
            const float gjk1 = -1.f + (j - 2 + k) * h;
            b[j] = (v - gj) / (gjk - gj) * b[j] + (gjk1 - v) / (gjk1 - gj1) * b[j + 1];
        }
    }
    __half* ap = A + n * KCOMB + IN3 + (long)i * NB;
    #pragma unroll
    for (int f = 0; f < NB; ++f) ap[f] = __float2half_rn(b[f]);
}

// ---------------------------------------------------------------------------
// out = part0 + part1 (split-K reduction, fixed order -> deterministic)
// ---------------------------------------------------------------------------
__global__ __launch_bounds__(256)
void add2_kernel(const float* __restrict__ p0, const float* __restrict__ p1,
                 float* __restrict__ out, int n)
{
    const int i = blockIdx.x * 1024 + threadIdx.x * 4;
    if (i >= n) return;
    float4 a = *(const float4*)(p0 + i);
    float4 b = *(const float4*)(p1 + i);
    a.x += b.x; a.y += b.y; a.z += b.z; a.w += b.w;
    *(float4*)(out + i) = a;
}

// ---------------------------------------------------------------------------
// Host launcher
// ---------------------------------------------------------------------------
extern "C" void kernel_launch(void* const* d_in, const int* in_sizes, int n_in,
                              void* d_out, int out_size)
{
    (void)in_sizes; (void)n_in; (void)out_size;

    const float* tok[NVIEW] = {(const float*)d_in[0], (const float*)d_in[1], (const float*)d_in[2]};
    const float* wq = (const float*)d_in[3];
    const float* bq = (const float*)d_in[4];
    const float* wk = (const float*)d_in[5];
    const float* bk = (const float*)d_in[6];
    const float* wv = (const float*)d_in[7];
    const float* bv = (const float*)d_in[8];
    // d_in[9] = view_emb: per-query constant bias -> softmax-invariant -> unused
    const float* lng[NVIEW] = {(const float*)d_in[10], (const float*)d_in[12], (const float*)d_in[14]};
    const float* lnb[NVIEW] = {(const float*)d_in[11], (const float*)d_in[13], (const float*)d_in[15]};
    const float* bw = (const float*)d_in[16];
    const float* sw = (const float*)d_in[17];
    const float* sc = (const float*)d_in[18];

    __half *ptok, *pwqkv, *pqkv, *pvt, *ps, *pa, *pw;
    float *pbqkv, *att, *x, *ppart;
    cudaGetSymbolAddress((void**)&ptok,  g_tok);
    cudaGetSymbolAddress((void**)&pwqkv, g_wqkv);
    cudaGetSymbolAddress((void**)&pbqkv, g_bqkv);
    cudaGetSymbolAddress((void**)&pqkv,  g_qkv);
    cudaGetSymbolAddress((void**)&pvt,   g_vt);
    cudaGetSymbolAddress((void**)&ps,    g_s);
    cudaGetSymbolAddress((void**)&att,   g_att);
    cudaGetSymbolAddress((void**)&x,     g_x);
    cudaGetSymbolAddress((void**)&pa,    g_a);
    cudaGetSymbolAddress((void**)&pw,    g_w);
    cudaGetSymbolAddress((void**)&ppart, g_part);

    const int SMEM = STAGES * STG_H * 2 * (int)sizeof(__half);   // 81920 B
    cudaFuncSetAttribute(hgemm<true>,  cudaFuncAttributeMaxDynamicSharedMemorySize, SMEM);
    cudaFuncSetAttribute(hgemm<false>, cudaFuncAttributeMaxDynamicSharedMemorySize, SMEM);

    const long qkvSlice = (long)SEQ * QKVN;
    const long sStride  = (long)SEQ * SEQ;

    // 0) pack tokens (fp16) and qkv weights
    const int ntok = NROWS * DIM;
    for (int vi = 0; vi < NVIEW; ++vi)
        round_copy_h<<<(ntok + 1023) / 1024, 256>>>(tok[vi], ptok + (long)vi * ntok, ntok);
    build_wqkv<<<(QKVN * DIM + 255) / 256, 256>>>(wq, wk, wv, bq, bk, bv, pwqkv, pbqkv);

    // 1) fused QKV: [24576,768] = tok @ Wqkv^T + bqkv -> fp16
    {
        dim3 grid(QKVN / 128, ROWS3 / 128, 1);
        hgemm<true><<<grid, 256, SMEM>>>(ptok, DIM, pwqkv, DIM, pqkv, QKVN,
                                         DIM, 0, 0, 0, pbqkv);
    }

    // 1b) transpose V slices -> g_vt
    {
        dim3 grid(SEQ / 32, DIM / 32, NVB);
        transpose_v<<<grid, 256>>>(pqkv, pvt);
    }

    // 2) scores = Q @ K^T (fp16 out), all 6 slices
    {
        dim3 grid(SEQ / 128, SEQ / 128, NVB);
        hgemm<true><<<grid, 256, SMEM>>>(pqkv, QKVN, pqkv + DIM, QKVN, ps, SEQ,
                                         DIM, qkvSlice, qkvSlice, sStride, nullptr);
    }

    // 3) softmax(scores / 16) in place -> fp16 probs
    softmax_h<<<NVB * SEQ, 256>>>(ps, 0.0625f);

    // 4) att = P @ Vt^T (NT, fp32 out)
    {
        dim3 grid(DIM / 128, SEQ / 128, NVB);
        hgemm<false><<<grid, 256, SMEM>>>(ps, SEQ, pvt, SEQ, att, DIM,
                                          SEQ, sStride, (long)DIM * SEQ, (long)SEQ * DIM, nullptr);
    }

    // 5) LayerNorm(att + tokens) -> concat x (fp32)
    for (int vi = 0; vi < NVIEW; ++vi)
        resid_ln_kernel<<<NROWS, 256>>>(att + (long)vi * NROWS * DIM, tok[vi],
                                        lng[vi], lnb[vi], x, vi);

    // 6) combined weight / combined A (fp16)
    build_w_kernel<<<(DIM * IN3 + 255) / 256, 256>>>(bw, sw, sc, pw);
    build_a_kernel<<<(int)(((long)NROWS * IN3 + 255) / 256), 256>>>(x, pa);

    // 7) out = A @ W^T via split-K=2 (256 CTAs), then deterministic add
    {
        dim3 grid(DIM / 128, NROWS / 128, 2);
        hgemm<false><<<grid, 256, SMEM>>>(pa, KCOMB, pw, KCOMB, ppart, DIM,
                                          KCOMB / 2, KCOMB / 2, KCOMB / 2,
                                          (long)NROWS * DIM, nullptr);
        add2_kernel<<<(NROWS * DIM + 1023) / 1024, 256>>>(
            ppart, ppart + (long)NROWS * DIM, (float*)d_out, NROWS * DIM);
    }
}